// round 11
// baseline (speedup 1.0000x reference)
#include <cuda_runtime.h>
#include <cuda_bf16.h>
#include <math.h>

// H = [[1.2, c],[c, 0.01]], c = cos(theta)
// inv = 1/(1.2*0.01 - c^2) * [[0.01, -c],[-c, 1.2]]
//
// Numerics (verified, rel_err 1.92e-5): bulk = __cosf + rcp.approx;
// near-singular elements (|det| < 1e-5) redo with correctly-rounded fp32 cos
// (via fp64) + correctly-rounded divide — they own the reference L2 norm.
//
// Perf history:
//   R7: 1 elem/thread                      -> 35.3us (MLP=1 bound)
//   R8: 4 elem/thread, front-batched LDGs  -> 29.9us, DRAM 54.8% (MLP=4 sweet spot)
//   R9: 8 elem/thread                      -> 31.5us REGRESSED (L1tex queue:
//       oe*MLP_p1 ~ 24 > Q_th ~ 16 -> cross-CTA contention)
//   R10: keep MLP=4 bursts; persistent grid (148*8 CTAs, single wave) +
//        grid-stride chunks with DOUBLE-BUFFERED loads: next chunk's 4 LDGs
//        issue before current chunk's compute+stores. Sustained MLP=4 for the
//        warp's whole life; no wave transitions; no per-CTA re-warmup.

__device__ __forceinline__ float rcp_approx(float x) {
    float r;
    asm("rcp.approx.f32 %0, %1;" : "=f"(r) : "f"(x));
    return r;
}

__device__ __forceinline__ float4 invert_one(float t)
{
    const float ad = 1.2f * 0.01f;

    float c   = __cosf(t);
    float det = __fsub_rn(ad, __fmul_rn(c, c));
    float r   = rcp_approx(det);

    if (fabsf(det) < 1e-5f) {                 // ~0.005% of elements
        c   = (float)cos((double)t);
        det = __fsub_rn(ad, __fmul_rn(c, c));
        r   = __fdiv_rn(1.0f, det);
    }

    float4 v;
    v.x = __fmul_rn(0.01f, r);
    v.y = __fmul_rn(-c,    r);
    v.z = v.y;
    v.w = __fmul_rn(1.2f,  r);
    return v;
}

__global__ __launch_bounds__(256) void inv2x2_kernel_v10(
    const float* __restrict__ theta,
    float4* __restrict__ out,
    int n,
    int nChunks)            // number of FULL 1024-element chunks
{
    const int T = 256;
    const int tid = threadIdx.x;
    const int stride = gridDim.x;

    int c = blockIdx.x;
    if (c < nChunks) {
        // Prologue: load chunk c (4 coalesced 128B warp LDGs, MLP_p1 = 4).
        int base = c * (T * 4) + tid;
        float a0 = __ldg(&theta[base]);
        float a1 = __ldg(&theta[base +     T]);
        float a2 = __ldg(&theta[base + 2 * T]);
        float a3 = __ldg(&theta[base + 3 * T]);

        for (;;) {
            // Issue NEXT chunk's loads before touching current values —
            // keeps 4 loads in flight while compute+stores drain.
            int cn = c + stride;
            bool more = cn < nChunks;
            int nbase = cn * (T * 4) + tid;
            float b0, b1, b2, b3;
            if (more) {
                b0 = __ldg(&theta[nbase]);
                b1 = __ldg(&theta[nbase +     T]);
                b2 = __ldg(&theta[nbase + 2 * T]);
                b3 = __ldg(&theta[nbase + 3 * T]);
            }

            // Compute + store current chunk: one coalesced 512B/warp STG.128
            // per element, interleaved (proven R8 shape).
            out[base]         = invert_one(a0);
            out[base +     T] = invert_one(a1);
            out[base + 2 * T] = invert_one(a2);
            out[base + 3 * T] = invert_one(a3);

            if (!more) break;
            c = cn; base = nbase;
            a0 = b0; a1 = b1; a2 = b2; a3 = b3;
        }
    }

    // Remainder elements beyond the last full chunk (none for n = 8388608).
    for (int i = nChunks * (T * 4) + blockIdx.x * T + tid; i < n;
         i += stride * T)
        out[i] = invert_one(__ldg(&theta[i]));
}

extern "C" void kernel_launch(void* const* d_in, const int* in_sizes, int n_in,
                              void* d_out, int out_size) {
    const float* theta = (const float*)d_in[0];
    float4* out = (float4*)d_out;
    int n = in_sizes[0];                        // 8388608

    const int threads = 256;
    int nChunks = n / (threads * 4);            // 8192 full chunks
    int blocks = 148 * 8;                       // single resident wave
    if (blocks > nChunks && nChunks > 0) blocks = nChunks;
    if (blocks == 0) blocks = 1;
    inv2x2_kernel_v10<<<blocks, threads>>>(theta, out, n, nChunks);
}

// round 12
// speedup vs baseline: 1.0656x; 1.0656x over previous
#include <cuda_runtime.h>
#include <cuda_bf16.h>
#include <math.h>

// H = [[1.2, c],[c, 0.01]], c = cos(theta)
// inv = 1/(1.2*0.01 - c^2) * [[0.01, -c],[-c, 1.2]]
//
// Numerics (verified, rel_err 1.92e-5): bulk = __cosf + rcp.approx;
// near-singular elements (|det| < 1e-5) redo with correctly-rounded fp32 cos
// (via fp64) + correctly-rounded divide — they own the reference L2 norm.
//
// Perf history:
//   R7:  1 elem/thread                      -> 35.3us (MLP=1 bound)
//   R8:  4 elem/thread, front-batched LDGs,
//        strided-by-T stores (4-line STGs)  -> 29.9us  BEST (DRAM 54.8%)
//   R9:  8 elem/thread                      -> 31.5us REGRESSED (L1tex queue)
//   R10: persistent grid + double buffer    -> 33.2us REGRESSED (occ 54%, regs 40)
//   R11: exact R8 skeleton; the only change is divergence handling — the 4
//        per-element data-dependent ifs (4 BSSY/BSYNC envelopes per thread,
//        paid even when never taken) become ONE warp-uniform ballot-gated
//        branch covering the rare fp64 repair of all 4 elements. The fp64
//        body leaves the hot path; hot-path regs drop.

__device__ __forceinline__ float rcp_approx(float x) {
    float r;
    asm("rcp.approx.f32 %0, %1;" : "=f"(r) : "f"(x));
    return r;
}

__device__ __forceinline__ float4 pack_inv(float c, float r)
{
    float4 v;
    v.x = __fmul_rn(0.01f, r);
    v.y = __fmul_rn(-c,    r);
    v.z = v.y;
    v.w = __fmul_rn(1.2f,  r);
    return v;
}

// Exact repair for a near-singular element: correctly-rounded fp32 cos via
// fp64, reference op-order det, correctly-rounded divide.
__device__ __noinline__ void fix_exact(float t, float& c, float& r)
{
    const float ad = 1.2f * 0.01f;
    c = (float)cos((double)t);
    float det = __fsub_rn(ad, __fmul_rn(c, c));
    r = __fdiv_rn(1.0f, det);
}

__global__ __launch_bounds__(256) void inv2x2_kernel_v11(
    const float* __restrict__ theta,
    float4* __restrict__ out,
    int n)
{
    const int T = 256;                          // blockDim.x
    int base = blockIdx.x * (T * 4) + threadIdx.x;

    const float ad = 1.2f * 0.01f;              // fl(fl(1.2)*fl(0.01))
    const float thresh = 1e-5f;

    if (base + 3 * T < n) {
        // Front-batched independent loads: 4 coalesced 128B warp LDGs in
        // flight before any compute (MLP_p1 = 4). Proven R8 shape.
        float t0 = __ldg(&theta[base]);
        float t1 = __ldg(&theta[base +     T]);
        float t2 = __ldg(&theta[base + 2 * T]);
        float t3 = __ldg(&theta[base + 3 * T]);

        // Fast path for all 4 elements — branch-free, MUFU chains pipeline.
        float c0 = __cosf(t0), c1 = __cosf(t1), c2 = __cosf(t2), c3 = __cosf(t3);
        float d0 = __fsub_rn(ad, __fmul_rn(c0, c0));
        float d1 = __fsub_rn(ad, __fmul_rn(c1, c1));
        float d2 = __fsub_rn(ad, __fmul_rn(c2, c2));
        float d3 = __fsub_rn(ad, __fmul_rn(c3, c3));
        float r0 = rcp_approx(d0), r1 = rcp_approx(d1);
        float r2 = rcp_approx(d2), r3 = rcp_approx(d3);

        // Rare repair (~0.005% of elements): single warp-uniform gate.
        bool n0 = fabsf(d0) < thresh, n1 = fabsf(d1) < thresh;
        bool n2 = fabsf(d2) < thresh, n3 = fabsf(d3) < thresh;
        if (__ballot_sync(0xFFFFFFFFu, n0 | n1 | n2 | n3)) {
            if (n0) fix_exact(t0, c0, r0);
            if (n1) fix_exact(t1, c1, r1);
            if (n2) fix_exact(t2, c2, r2);
            if (n3) fix_exact(t3, c3, r3);
        }

        // Stores: strided-by-T -> each STG.128 writes 512B contiguous per
        // warp (4 lines). Interleaving left to ptxas.
        out[base]         = pack_inv(c0, r0);
        out[base +     T] = pack_inv(c1, r1);
        out[base + 2 * T] = pack_inv(c2, r2);
        out[base + 3 * T] = pack_inv(c3, r3);
    } else {
        // Tail (unused for n = 8388608, divisible by 1024).
        for (int k = 0; k < 4; k++) {
            int i = base + k * T;
            if (i < n) {
                float t = __ldg(&theta[i]);
                float c = __cosf(t);
                float d = __fsub_rn(ad, __fmul_rn(c, c));
                float r = rcp_approx(d);
                if (fabsf(d) < thresh) fix_exact(t, c, r);
                out[i] = pack_inv(c, r);
            }
        }
    }
}

extern "C" void kernel_launch(void* const* d_in, const int* in_sizes, int n_in,
                              void* d_out, int out_size) {
    const float* theta = (const float*)d_in[0];
    float4* out = (float4*)d_out;
    int n = in_sizes[0];                        // 8388608

    const int threads = 256;
    int elems_per_block = threads * 4;          // 1024
    int blocks = (n + elems_per_block - 1) / elems_per_block;   // 8192
    inv2x2_kernel_v11<<<blocks, threads>>>(theta, out, n);
}

// round 13
// speedup vs baseline: 1.0800x; 1.0135x over previous
#include <cuda_runtime.h>
#include <cuda_bf16.h>
#include <math.h>

// H = [[1.2, c],[c, 0.01]], c = cos(theta)
// inv = 1/(1.2*0.01 - c^2) * [[0.01, -c],[-c, 1.2]]
//
// Numerics (verified, rel_err 1.92e-5): bulk = __cosf + rcp.approx;
// near-singular elements (|det| < 1e-5, ~0.005%) redo with correctly-rounded
// fp32 cos (via fp64) + correctly-rounded divide — they own the ref L2 norm.
//
// Final structure = R8, the empirical optimum. Search record:
//   R7:  1 elem/thread (MLP=1)                    35.3us
//   R8:  4 elem/thread, front-batched scalar LDGs,
//        per-element interleaved STG.128          29.9us  << BEST
//   R9:  8 elem/thread (L1tex queue overflow)     31.5us
//   R10: persistent grid + double buffering       33.2us (occ 54%, regs 40)
//   R11: batched compute + ballot-gated repair    31.2us (store burst: L1 69%)
// Irreducible traffic 160MB; R8's ncu 25.0us sits at the ~24.6us achievable
// write-dominated HBM floor. Store PACING (one STG between MUFU chains) and
// load MLP=4 are both load-bearing — do not batch stores, do not raise ILP.

__device__ __forceinline__ float rcp_approx(float x) {
    float r;
    asm("rcp.approx.f32 %0, %1;" : "=f"(r) : "f"(x));
    return r;
}

__device__ __forceinline__ float4 invert_one(float t)
{
    const float ad = 1.2f * 0.01f;

    float c   = __cosf(t);
    float det = __fsub_rn(ad, __fmul_rn(c, c));
    float r   = rcp_approx(det);

    if (fabsf(det) < 1e-5f) {                 // ~0.005% of elements
        c   = (float)cos((double)t);
        det = __fsub_rn(ad, __fmul_rn(c, c));
        r   = __fdiv_rn(1.0f, det);
    }

    float4 v;
    v.x = __fmul_rn(0.01f, r);
    v.y = __fmul_rn(-c,    r);
    v.z = v.y;
    v.w = __fmul_rn(1.2f,  r);
    return v;
}

__global__ __launch_bounds__(256) void inv2x2_kernel_v12(
    const float* __restrict__ theta,
    float4* __restrict__ out,
    int n)
{
    const int T = 256;                         // blockDim.x
    int base = blockIdx.x * (T * 4) + threadIdx.x;

    if (base + 3 * T < n) {
        // Front-batched independent loads: 4 LDGs in flight per warp before
        // any compute (MLP_p1 = 4). Each is a fully coalesced 128B warp load.
        float t0 = __ldg(&theta[base]);
        float t1 = __ldg(&theta[base +     T]);
        float t2 = __ldg(&theta[base + 2 * T]);
        float t3 = __ldg(&theta[base + 3 * T]);

        // Compute + store interleaved; each store is a coalesced 512B/warp
        // STG.128 spaced between MUFU chains (store pacing is load-bearing).
        out[base]         = invert_one(t0);
        out[base +     T] = invert_one(t1);
        out[base + 2 * T] = invert_one(t2);
        out[base + 3 * T] = invert_one(t3);
    } else {
        // Tail (unused for n = 8388608, divisible by 1024).
        for (int k = 0; k < 4; k++) {
            int i = base + k * T;
            if (i < n) out[i] = invert_one(__ldg(&theta[i]));
        }
    }
}

extern "C" void kernel_launch(void* const* d_in, const int* in_sizes, int n_in,
                              void* d_out, int out_size) {
    const float* theta = (const float*)d_in[0];
    float4* out = (float4*)d_out;
    int n = in_sizes[0];                       // 8388608

    const int threads = 256;
    int elems_per_block = threads * 4;         // 1024
    int blocks = (n + elems_per_block - 1) / elems_per_block;   // 8192
    inv2x2_kernel_v12<<<blocks, threads>>>(theta, out, n);
}

// round 14
// speedup vs baseline: 1.1220x; 1.0389x over previous
#include <cuda_runtime.h>
#include <cuda_bf16.h>
#include <math.h>

// H = [[1.2, c],[c, 0.01]], c = cos(theta)
// inv = 1/(1.2*0.01 - c^2) * [[0.01, -c],[-c, 1.2]]
//
// Numerics (verified, rel_err 1.92e-5): bulk = __cosf + rcp.approx;
// near-singular elements (|det| < 1e-5, ~0.005%) redo with correctly-rounded
// fp32 cos (via fp64) + correctly-rounded divide — they own the ref L2 norm.
//
// Structure = R8 (empirical optimum; every mutation regressed):
//   R7:  1 elem/thread (MLP=1)                    35.3us
//   R8:  4 elem/thread, front-batched scalar LDGs,
//        per-element interleaved STG.128          29.9us  << BEST
//   R9:  8 elem/thread (L1tex queue overflow)     31.5us
//   R10: persistent grid + double buffering       33.2us
//   R11: batched compute + ballot-gated repair    31.2us (store burst)
//   R12: R8 re-run                                30.8us (noise band)
//   R13: R8 + __ldcs on the read-once input (evict-first) — frees L2
//        residency/victim bandwidth for the 128MB write stream. Store-side
//        policy stays DEFAULT (R4 proved streaming hints on stores regress).
//
// 160MB irreducible traffic; ~25us ncu sits at the write-dominated HBM floor.

__device__ __forceinline__ float rcp_approx(float x) {
    float r;
    asm("rcp.approx.f32 %0, %1;" : "=f"(r) : "f"(x));
    return r;
}

__device__ __forceinline__ float4 invert_one(float t)
{
    const float ad = 1.2f * 0.01f;

    float c   = __cosf(t);
    float det = __fsub_rn(ad, __fmul_rn(c, c));
    float r   = rcp_approx(det);

    if (fabsf(det) < 1e-5f) {                 // ~0.005% of elements
        c   = (float)cos((double)t);
        det = __fsub_rn(ad, __fmul_rn(c, c));
        r   = __fdiv_rn(1.0f, det);
    }

    float4 v;
    v.x = __fmul_rn(0.01f, r);
    v.y = __fmul_rn(-c,    r);
    v.z = v.y;
    v.w = __fmul_rn(1.2f,  r);
    return v;
}

__global__ __launch_bounds__(256) void inv2x2_kernel_v13(
    const float* __restrict__ theta,
    float4* __restrict__ out,
    int n)
{
    const int T = 256;                         // blockDim.x
    int base = blockIdx.x * (T * 4) + threadIdx.x;

    if (base + 3 * T < n) {
        // Front-batched independent loads: 4 LDGs in flight per warp before
        // any compute (MLP_p1 = 4), each a coalesced 128B warp load.
        // Evict-first: input is read exactly once; don't let it squat in L2.
        float t0 = __ldcs(&theta[base]);
        float t1 = __ldcs(&theta[base +     T]);
        float t2 = __ldcs(&theta[base + 2 * T]);
        float t3 = __ldcs(&theta[base + 3 * T]);

        // Compute + store interleaved; each store is a coalesced 512B/warp
        // STG.128 spaced between MUFU chains (store pacing is load-bearing).
        out[base]         = invert_one(t0);
        out[base +     T] = invert_one(t1);
        out[base + 2 * T] = invert_one(t2);
        out[base + 3 * T] = invert_one(t3);
    } else {
        // Tail (unused for n = 8388608, divisible by 1024).
        for (int k = 0; k < 4; k++) {
            int i = base + k * T;
            if (i < n) out[i] = invert_one(__ldcs(&theta[i]));
        }
    }
}

extern "C" void kernel_launch(void* const* d_in, const int* in_sizes, int n_in,
                              void* d_out, int out_size) {
    const float* theta = (const float*)d_in[0];
    float4* out = (float4*)d_out;
    int n = in_sizes[0];                       // 8388608

    const int threads = 256;
    int elems_per_block = threads * 4;         // 1024
    int blocks = (n + elems_per_block - 1) / elems_per_block;   // 8192
    inv2x2_kernel_v13<<<blocks, threads>>>(theta, out, n);
}